// round 1
// baseline (speedup 1.0000x reference)
#include <cuda_runtime.h>

#define N_ELEC 62
#define IN_CH  5
#define HID    32
#define N_CLS  3
#define GPB    8      // graphs per block
#define NTHR   512    // GPB * 64

// Precomputed S = M^2 where M = D^{-1/2} A D^{-1/2} (62x62, batch-invariant)
__device__ float g_S[N_ELEC * N_ELEC];

// ---------------------------------------------------------------------------
// Kernel 1: build A from tril params, normalize, square. One block.
// ---------------------------------------------------------------------------
__global__ void rgnn_setup_kernel(const float* __restrict__ adj_tril) {
    __shared__ float M[N_ELEC * N_ELEC];
    __shared__ float dinv[N_ELEC];
    const int tid = threadIdx.x;

    // A[i][j] = adj_tril[t], t = max*(max+1)/2 + min (np.tril_indices order),
    // symmetrized with original diagonal (A + A^T - diag matches this exactly).
    for (int idx = tid; idx < N_ELEC * N_ELEC; idx += blockDim.x) {
        int i = idx / N_ELEC, j = idx % N_ELEC;
        int a = i > j ? i : j;
        int b = i > j ? j : i;
        M[idx] = adj_tril[a * (a + 1) / 2 + b];
    }
    __syncthreads();

    // deg[i] = sum_j |A[i][j]|; dinv = rsqrt(deg) (0 if deg==0)
    if (tid < N_ELEC) {
        float d = 0.f;
        for (int j = 0; j < N_ELEC; j++) d += fabsf(M[tid * N_ELEC + j]);
        dinv[tid] = (d > 0.f) ? rsqrtf(d) : 0.f;
    }
    __syncthreads();

    // M = dinv[i] * A * dinv[j]  (in place; each element touched by one thread)
    for (int idx = tid; idx < N_ELEC * N_ELEC; idx += blockDim.x) {
        int i = idx / N_ELEC, j = idx % N_ELEC;
        M[idx] = dinv[i] * M[idx] * dinv[j];
    }
    __syncthreads();

    // S = M @ M
    for (int idx = tid; idx < N_ELEC * N_ELEC; idx += blockDim.x) {
        int i = idx / N_ELEC, j = idx % N_ELEC;
        float s = 0.f;
        for (int k = 0; k < N_ELEC; k++)
            s += M[i * N_ELEC + k] * M[k * N_ELEC + j];
        g_S[idx] = s;
    }
}

// ---------------------------------------------------------------------------
// Kernel 2: per graph  out = F @ relu(W @ (S X)^T + b) summed over nodes + fc_b
// Thread layout: tid = g*64 + j  (g = graph-in-block 0..7, j = node 0..61)
// ---------------------------------------------------------------------------
__global__ __launch_bounds__(NTHR) void rgnn_main_kernel(
    const float* __restrict__ x,       // [B*62, 5]
    const float* __restrict__ lin_w,   // [32, 5]
    const float* __restrict__ lin_b,   // [32]
    const float* __restrict__ fc_w,    // [3, 32]
    const float* __restrict__ fc_b,    // [3]
    float* __restrict__ out,           // [B, 3]
    int B)
{
    __shared__ float Ssh[N_ELEC * N_ELEC];          // 15376 B
    __shared__ float Xsh[GPB][N_ELEC][8];           // padded to 8 for LDS.128
    __shared__ float Wsh[HID][IN_CH];
    __shared__ float bsh[HID];
    __shared__ float Fsh[N_CLS][HID];
    __shared__ float red[GPB][2][N_CLS];            // two half-warps per graph

    const int tid = threadIdx.x;
    const int g0  = blockIdx.x * GPB;

    for (int idx = tid; idx < N_ELEC * N_ELEC; idx += NTHR)
        Ssh[idx] = g_S[idx];
    if (tid < HID * IN_CH)                  (&Wsh[0][0])[tid] = lin_w[tid];
    else if (tid < HID * IN_CH + HID)       bsh[tid - HID * IN_CH] = lin_b[tid - HID * IN_CH];
    else if (tid < HID * IN_CH + HID + N_CLS * HID)
        (&Fsh[0][0])[tid - HID * IN_CH - HID] = fc_w[tid - HID * IN_CH - HID];

    // Stage 8 graphs of X (coalesced global read; pad channels 5..7 unused)
    {
        const float* xg = x + (size_t)g0 * N_ELEC * IN_CH;
        int nvalid = (B - g0) < GPB ? (B - g0) : GPB;
        int total = nvalid * N_ELEC * IN_CH;
        for (int idx = tid; idx < total; idx += NTHR) {
            int gi = idx / (N_ELEC * IN_CH);
            int r  = idx % (N_ELEC * IN_CH);
            Xsh[gi][r / IN_CH][r % IN_CH] = xg[idx];
        }
    }
    __syncthreads();

    const int g = tid >> 6;          // 0..7
    const int j = tid & 63;          // node (62 valid)
    const bool valid = (j < N_ELEC) && (g0 + g < B);

    float o0 = 0.f, o1 = 0.f, o2 = 0.f;

    if (valid) {
        // y_j = sum_i S[i][j] * x_i   (5 channels)
        float a0 = 0.f, a1 = 0.f, a2 = 0.f, a3 = 0.f, a4 = 0.f;
        #pragma unroll 2
        for (int i = 0; i < N_ELEC; i++) {
            float s = Ssh[i * N_ELEC + j];                       // conflict-free
            float4 xv = *(const float4*)&Xsh[g][i][0];           // broadcast
            float x4  = Xsh[g][i][4];                            // broadcast
            a0 = fmaf(s, xv.x, a0);
            a1 = fmaf(s, xv.y, a1);
            a2 = fmaf(s, xv.z, a2);
            a3 = fmaf(s, xv.w, a3);
            a4 = fmaf(s, x4,   a4);
        }
        // h = relu(W y + b); fuse pooling+fc: o_c += F[c][o] * h[o]
        #pragma unroll
        for (int o = 0; o < HID; o++) {
            float v = bsh[o];
            v = fmaf(Wsh[o][0], a0, v);
            v = fmaf(Wsh[o][1], a1, v);
            v = fmaf(Wsh[o][2], a2, v);
            v = fmaf(Wsh[o][3], a3, v);
            v = fmaf(Wsh[o][4], a4, v);
            v = fmaxf(v, 0.f);
            o0 = fmaf(Fsh[0][o], v, o0);
            o1 = fmaf(Fsh[1][o], v, o1);
            o2 = fmaf(Fsh[2][o], v, o2);
        }
    }

    // Reduce the 3 outputs across the 64 threads (2 full warps) of each graph
    #pragma unroll
    for (int off = 16; off > 0; off >>= 1) {
        o0 += __shfl_down_sync(0xffffffffu, o0, off);
        o1 += __shfl_down_sync(0xffffffffu, o1, off);
        o2 += __shfl_down_sync(0xffffffffu, o2, off);
    }
    const int lane = tid & 31;
    const int half = (tid >> 5) & 1;
    if (lane == 0) {
        red[g][half][0] = o0;
        red[g][half][1] = o1;
        red[g][half][2] = o2;
    }
    __syncthreads();

    if (j < N_CLS && (g0 + g) < B)
        out[(size_t)(g0 + g) * N_CLS + j] =
            red[g][0][j] + red[g][1][j] + fc_b[j];
}

// ---------------------------------------------------------------------------
extern "C" void kernel_launch(void* const* d_in, const int* in_sizes, int n_in,
                              void* d_out, int out_size) {
    const float* x        = (const float*)d_in[0];
    const float* adj_tril = (const float*)d_in[1];
    const float* lin_w    = (const float*)d_in[2];
    const float* lin_b    = (const float*)d_in[3];
    const float* fc_w     = (const float*)d_in[4];
    const float* fc_b     = (const float*)d_in[5];
    // d_in[6] edge_index, d_in[7] batch_idx: structurally redundant (dense
    // per-graph all-pairs graph, identical across batch) — not needed.

    const int B = in_sizes[0] / (N_ELEC * IN_CH);

    rgnn_setup_kernel<<<1, 1024>>>(adj_tril);

    const int grid = (B + GPB - 1) / GPB;
    rgnn_main_kernel<<<grid, NTHR>>>(x, lin_w, lin_b, fc_w, fc_b,
                                     (float*)d_out, B);
}

// round 3
// speedup vs baseline: 1.0706x; 1.0706x over previous
#include <cuda_runtime.h>

#define N_ELEC 62
#define IN_CH  5
#define HID    32
#define N_CLS  3
#define SPITCH 64          // padded row stride for S / M
#define GPB    16          // graphs per block
#define NPAIR  (GPB/2)
#define NTHR   256

// Precomputed S = M^2, M = D^{-1/2} A D^{-1/2}; padded [62][64], cols 62..63 = 0
__device__ float g_S[N_ELEC * SPITCH];

#define FMA2(acc, a, b) \
    asm("fma.rn.f32x2 %0, %1, %2, %0;" : "+l"(acc) : "l"(a), "l"(b))
#define PACK2(d, s) \
    asm("mov.b64 %0, {%1, %1};" : "=l"(d) : "f"(s))
#define UNPK2(lo, hi, v) \
    asm("mov.b64 {%0, %1}, %2;" : "=f"(lo), "=f"(hi) : "l"(v))

// ---------------------------------------------------------------------------
// Setup: build A from tril, GCN-normalize, square. One block, reg-blocked MM.
// ---------------------------------------------------------------------------
__global__ void rgnn_setup_kernel(const float* __restrict__ adj_tril) {
    __shared__ float M[N_ELEC * SPITCH];
    __shared__ float dinv[N_ELEC];
    const int tid = threadIdx.x;

    for (int idx = tid; idx < N_ELEC * N_ELEC; idx += blockDim.x) {
        int i = idx / N_ELEC, j = idx % N_ELEC;
        int a = i > j ? i : j;
        int b = i > j ? j : i;
        M[i * SPITCH + j] = adj_tril[a * (a + 1) / 2 + b];
    }
    __syncthreads();

    if (tid < N_ELEC) {
        float d = 0.f;
        for (int j = 0; j < N_ELEC; j++) d += fabsf(M[tid * SPITCH + j]);
        dinv[tid] = (d > 0.f) ? rsqrtf(d) : 0.f;
    }
    __syncthreads();

    for (int idx = tid; idx < N_ELEC * N_ELEC; idx += blockDim.x) {
        int i = idx / N_ELEC, j = idx % N_ELEC;
        M[i * SPITCH + j] = dinv[i] * M[i * SPITCH + j] * dinv[j];
    }
    if (tid < N_ELEC * 2) {             // zero pad columns 62, 63
        int i = tid >> 1, j = N_ELEC + (tid & 1);
        M[i * SPITCH + j] = 0.f;
    }
    __syncthreads();

    // S = M @ M : thread t -> row i = t>>2, 16-wide j block j0 = (t&3)*16
    if (tid < N_ELEC * 4) {
        const int i  = tid >> 2;
        const int j0 = (tid & 3) * 16;
        float acc[16];
        #pragma unroll
        for (int q = 0; q < 16; q++) acc[q] = 0.f;
        for (int k = 0; k < N_ELEC; k++) {
            float s = M[i * SPITCH + k];
            const float4* mr = (const float4*)&M[k * SPITCH + j0];
            #pragma unroll
            for (int q = 0; q < 4; q++) {
                float4 v = mr[q];
                acc[4*q+0] = fmaf(s, v.x, acc[4*q+0]);
                acc[4*q+1] = fmaf(s, v.y, acc[4*q+1]);
                acc[4*q+2] = fmaf(s, v.z, acc[4*q+2]);
                acc[4*q+3] = fmaf(s, v.w, acc[4*q+3]);
            }
        }
        #pragma unroll
        for (int q = 0; q < 16; q++) g_S[i * SPITCH + j0 + q] = acc[q];
    }
}

// ---------------------------------------------------------------------------
// Main: phase A = pair-packed propagation (y = S x), phase B = warp-per-graph
// relu(Wy+b) -> pool -> fc, all f32x2 where possible.
// ---------------------------------------------------------------------------
__global__ __launch_bounds__(NTHR) void rgnn_main_kernel(
    const float* __restrict__ x, const float* __restrict__ lin_w,
    const float* __restrict__ lin_b, const float* __restrict__ fc_w,
    const float* __restrict__ fc_b, float* __restrict__ out, int B)
{
    // Region layout:
    //  phase A: Ssh [62*64] floats (15872B) | Xp [NPAIR][62][6] float2 (23808B)
    //  phase B: Ysh [GPB][5][64] floats (20480B) aliases the same region
    __shared__ __align__(16) float smem[N_ELEC * SPITCH + NPAIR * N_ELEC * 6 * 2];
    float*  Ssh = smem;
    float2* Xp  = (float2*)(smem + N_ELEC * SPITCH);
    float*  Ysh = smem;
    __shared__ float Wsh[HID][IN_CH];
    __shared__ float bsh[HID];
    __shared__ float Fsh[N_CLS][HID];
    __shared__ float fcb[N_CLS];

    const int tid = threadIdx.x;
    const int g0  = blockIdx.x * GPB;

    // ---- stage S (vectorized), weights, and X (pair-interleaved) ----
    {
        const float4* gs4 = (const float4*)g_S;
        float4* ss4 = (float4*)Ssh;
        for (int idx = tid; idx < N_ELEC * SPITCH / 4; idx += NTHR)
            ss4[idx] = gs4[idx];
    }
    // Stage all 291 small-weight words, thread-count independent
    // (round-2 bug: branch chain assumed >=291 threads; NTHR is 256).
    for (int idx = tid; idx < HID * IN_CH + HID + N_CLS * HID + N_CLS; idx += NTHR) {
        if (idx < 160)      ((float*)Wsh)[idx] = lin_w[idx];
        else if (idx < 192) bsh[idx - 160] = lin_b[idx - 160];
        else if (idx < 288) ((float*)Fsh)[idx - 192] = fc_w[idx - 192];
        else                fcb[idx - 288] = fc_b[idx - 288];
    }
    {
        const float* xg = x + (size_t)g0 * N_ELEC * IN_CH;
        const int nv = (B - g0) < GPB ? (B - g0) : GPB;
        const int total = nv * N_ELEC * IN_CH;
        for (int idx = tid; idx < total; idx += NTHR) {
            int g = idx / (N_ELEC * IN_CH);
            int r = idx % (N_ELEC * IN_CH);
            int i = r / IN_CH, c = r % IN_CH;
            ((float*)&Xp[((g >> 1) * N_ELEC + i) * 6 + c])[g & 1] = xg[idx];
        }
    }
    __syncthreads();

    // ---- phase A: y_j = sum_i S[i][j] * x_i, 4 graphs/thread via f32x2 ----
    const int j   = tid & 63;
    const int grp = tid >> 6;            // 0..3, graphs 4*grp..4*grp+3
    unsigned long long a00=0,a01=0,a02=0,a03=0,a04=0;
    unsigned long long a10=0,a11=0,a12=0,a13=0,a14=0;

    if (j < N_ELEC) {
        const unsigned xb0 = (unsigned)__cvta_generic_to_shared(&Xp[(2*grp    ) * N_ELEC * 6]);
        const unsigned xb1 = (unsigned)__cvta_generic_to_shared(&Xp[(2*grp + 1) * N_ELEC * 6]);
        #pragma unroll 2
        for (int i = 0; i < N_ELEC; i++) {
            float s = Ssh[i * SPITCH + j];
            unsigned long long s2; PACK2(s2, s);
            unsigned long long q0,q1,q2,q3,q4;
            unsigned a = xb0 + i * 48;
            asm("ld.shared.v2.u64 {%0,%1}, [%2];"    : "=l"(q0), "=l"(q1) : "r"(a));
            asm("ld.shared.v2.u64 {%0,%1}, [%2+16];" : "=l"(q2), "=l"(q3) : "r"(a));
            asm("ld.shared.u64 %0, [%1+32];"         : "=l"(q4)           : "r"(a));
            FMA2(a00,s2,q0); FMA2(a01,s2,q1); FMA2(a02,s2,q2); FMA2(a03,s2,q3); FMA2(a04,s2,q4);
            unsigned b = xb1 + i * 48;
            asm("ld.shared.v2.u64 {%0,%1}, [%2];"    : "=l"(q0), "=l"(q1) : "r"(b));
            asm("ld.shared.v2.u64 {%0,%1}, [%2+16];" : "=l"(q2), "=l"(q3) : "r"(b));
            asm("ld.shared.u64 %0, [%1+32];"         : "=l"(q4)           : "r"(b));
            FMA2(a10,s2,q0); FMA2(a11,s2,q1); FMA2(a12,s2,q2); FMA2(a13,s2,q3); FMA2(a14,s2,q4);
        }
    }
    __syncthreads();   // all reads of Ssh/Xp complete; region can be reused

    if (j < N_ELEC) {
        const int gb = grp * 4;
        float lo, hi;
        #define YW(acc, gp, c) \
            UNPK2(lo, hi, acc); \
            Ysh[(gb + (gp))   * 320 + (c) * 64 + j] = lo; \
            Ysh[(gb + (gp)+1) * 320 + (c) * 64 + j] = hi;
        YW(a00, 0, 0) YW(a01, 0, 1) YW(a02, 0, 2) YW(a03, 0, 3) YW(a04, 0, 4)
        YW(a10, 2, 0) YW(a11, 2, 1) YW(a12, 2, 2) YW(a13, 2, 3) YW(a14, 2, 4)
        #undef YW
    }
    __syncthreads();

    // ---- phase B: warp per graph, lane = hidden unit o ----
    const int o  = tid & 31;
    const int gw = tid >> 5;             // 0..7
    const float w0 = Wsh[o][0], w1 = Wsh[o][1], w2 = Wsh[o][2],
                w3 = Wsh[o][3], w4 = Wsh[o][4];
    const float bo = bsh[o];
    const float f0 = Fsh[0][o], f1 = Fsh[1][o], f2 = Fsh[2][o];
    unsigned long long wd0,wd1,wd2,wd3,wd4,bd;
    PACK2(wd0,w0); PACK2(wd1,w1); PACK2(wd2,w2); PACK2(wd3,w3); PACK2(wd4,w4);
    PACK2(bd, bo);

    #pragma unroll
    for (int r = 0; r < 2; r++) {
        const int g = gw + r * 8;
        if (g0 + g < B) {
            const unsigned yb = (unsigned)__cvta_generic_to_shared(&Ysh[g * 320]);
            float ph = 0.f;
            #pragma unroll 2
            for (int j0 = 0; j0 < N_ELEC; j0 += 2) {
                unsigned long long y0,y1,y2,y3,y4;
                unsigned a = yb + j0 * 4;
                asm("ld.shared.u64 %0, [%1];"      : "=l"(y0) : "r"(a));
                asm("ld.shared.u64 %0, [%1+256];"  : "=l"(y1) : "r"(a));
                asm("ld.shared.u64 %0, [%1+512];"  : "=l"(y2) : "r"(a));
                asm("ld.shared.u64 %0, [%1+768];"  : "=l"(y3) : "r"(a));
                asm("ld.shared.u64 %0, [%1+1024];" : "=l"(y4) : "r"(a));
                unsigned long long v = bd;
                FMA2(v, wd0, y0); FMA2(v, wd1, y1); FMA2(v, wd2, y2);
                FMA2(v, wd3, y3); FMA2(v, wd4, y4);
                float lo, hi; UNPK2(lo, hi, v);
                ph += fmaxf(lo, 0.f);
                ph += fmaxf(hi, 0.f);
            }
            float s0 = f0 * ph, s1 = f1 * ph, s2 = f2 * ph;
            #pragma unroll
            for (int off = 16; off > 0; off >>= 1) {
                s0 += __shfl_down_sync(0xffffffffu, s0, off);
                s1 += __shfl_down_sync(0xffffffffu, s1, off);
                s2 += __shfl_down_sync(0xffffffffu, s2, off);
            }
            if (o == 0) {
                float* og = out + (size_t)(g0 + g) * N_CLS;
                og[0] = s0 + fcb[0];
                og[1] = s1 + fcb[1];
                og[2] = s2 + fcb[2];
            }
        }
    }
}

// ---------------------------------------------------------------------------
extern "C" void kernel_launch(void* const* d_in, const int* in_sizes, int n_in,
                              void* d_out, int out_size) {
    const float* x        = (const float*)d_in[0];
    const float* adj_tril = (const float*)d_in[1];
    const float* lin_w    = (const float*)d_in[2];
    const float* lin_b    = (const float*)d_in[3];
    const float* fc_w     = (const float*)d_in[4];
    const float* fc_b     = (const float*)d_in[5];
    // d_in[6] edge_index / d_in[7] batch_idx are structurally redundant.

    const int B = in_sizes[0] / (N_ELEC * IN_CH);

    rgnn_setup_kernel<<<1, 1024>>>(adj_tril);

    const int grid = (B + GPB - 1) / GPB;
    rgnn_main_kernel<<<grid, NTHR>>>(x, lin_w, lin_b, fc_w, fc_b,
                                     (float*)d_out, B);
}

// round 4
// speedup vs baseline: 1.4402x; 1.3453x over previous
#include <cuda_runtime.h>

#define N_ELEC 62
#define IN_CH  5
#define HID    32
#define N_CLS  3
#define SPITCH 64          // padded row stride for S / A
#define GPB    8           // graphs per block (4 f32x2 pairs)
#define NPAIR  (GPB/2)
#define NTHR   256

// Precomputed S = M^2, M = D^{-1/2} A D^{-1/2}; padded [62][64], cols 62..63 = 0
__device__ float g_S[N_ELEC * SPITCH];

#define FMA2(acc, a, b) \
    asm("fma.rn.f32x2 %0, %1, %2, %0;" : "+l"(acc) : "l"(a), "l"(b))
#define PACK2(d, s) \
    asm("mov.b64 %0, {%1, %1};" : "=l"(d) : "f"(s))
#define UNPK2(lo, hi, v) \
    asm("mov.b64 {%0, %1}, %2;" : "=f"(lo), "=f"(hi) : "l"(v))

// ---------------------------------------------------------------------------
// Setup: grid = 62 blocks, block b computes row b of S = M @ M.
// S[i][j] = dinv[j] * sum_k (dinv[i]*dinv[k]^2*A[i][k]) * A[k][j]
// ---------------------------------------------------------------------------
__global__ __launch_bounds__(128) void rgnn_setup_kernel(
    const float* __restrict__ adj_tril)
{
    __shared__ float A[N_ELEC * SPITCH];
    __shared__ float dinv[N_ELEC];
    __shared__ float t[N_ELEC];
    const int tid = threadIdx.x;
    const int i   = blockIdx.x;          // S row this block owns

    // Rebuild symmetric A from tril params (same data every block; L2-hot).
    for (int idx = tid; idx < N_ELEC * N_ELEC; idx += 128) {
        int r = idx / N_ELEC, c = idx % N_ELEC;
        int a = r > c ? r : c;
        int b = r > c ? c : r;
        A[r * SPITCH + c] = adj_tril[a * (a + 1) / 2 + b];
    }
    __syncthreads();

    if (tid < N_ELEC) {
        float d = 0.f;
        #pragma unroll 2
        for (int c = 0; c < N_ELEC; c++) d += fabsf(A[tid * SPITCH + c]);
        dinv[tid] = (d > 0.f) ? rsqrtf(d) : 0.f;
    }
    __syncthreads();

    if (tid < N_ELEC) {
        float dk = dinv[tid];
        t[tid] = dinv[i] * dk * dk * A[i * SPITCH + tid];
    }
    __syncthreads();

    if (tid < SPITCH) {
        const int j = tid;
        float s = 0.f;
        if (j < N_ELEC) {
            #pragma unroll 2
            for (int k = 0; k < N_ELEC; k++)
                s = fmaf(t[k], A[k * SPITCH + j], s);
            s *= dinv[j];
        }
        g_S[i * SPITCH + j] = s;         // pad cols 62..63 get 0
    }
}

// ---------------------------------------------------------------------------
// Main: phase A = pair-packed propagation (y = S x), one pair per thread;
// phase B = warp-per-graph relu(Wy+b) -> pool -> fc.
// ---------------------------------------------------------------------------
__global__ __launch_bounds__(NTHR) void rgnn_main_kernel(
    const float* __restrict__ x, const float* __restrict__ lin_w,
    const float* __restrict__ lin_b, const float* __restrict__ fc_w,
    const float* __restrict__ fc_b, float* __restrict__ out, int B)
{
    // phase A: Ssh [62*64] (15872B) | Xp [NPAIR][62][6] float2 (11904B)
    // phase B: Ysh [GPB][5][64] (10240B) aliases the same region
    __shared__ __align__(16) float smem[N_ELEC * SPITCH + NPAIR * N_ELEC * 6 * 2];
    float*  Ssh = smem;
    float2* Xp  = (float2*)(smem + N_ELEC * SPITCH);
    float*  Ysh = smem;
    __shared__ float Wsh[HID][IN_CH];
    __shared__ float bsh[HID];
    __shared__ float Fsh[N_CLS][HID];
    __shared__ float fcb[N_CLS];

    const int tid = threadIdx.x;
    const int g0  = blockIdx.x * GPB;

    // ---- stage S (float4), small weights (thread-count independent), X ----
    {
        const float4* gs4 = (const float4*)g_S;
        float4* ss4 = (float4*)Ssh;
        for (int idx = tid; idx < N_ELEC * SPITCH / 4; idx += NTHR)
            ss4[idx] = gs4[idx];
    }
    for (int idx = tid; idx < HID * IN_CH + HID + N_CLS * HID + N_CLS; idx += NTHR) {
        if (idx < 160)      ((float*)Wsh)[idx] = lin_w[idx];
        else if (idx < 192) bsh[idx - 160] = lin_b[idx - 160];
        else if (idx < 288) ((float*)Fsh)[idx - 192] = fc_w[idx - 192];
        else                fcb[idx - 288] = fc_b[idx - 288];
    }
    {
        const float* xg = x + (size_t)g0 * N_ELEC * IN_CH;
        const int nv = (B - g0) < GPB ? (B - g0) : GPB;
        const int total = nv * N_ELEC * IN_CH;
        for (int idx = tid; idx < total; idx += NTHR) {
            int g = idx / (N_ELEC * IN_CH);
            int r = idx % (N_ELEC * IN_CH);
            int i = r / IN_CH, c = r % IN_CH;
            ((float*)&Xp[((g >> 1) * N_ELEC + i) * 6 + c])[g & 1] = xg[idx];
        }
    }
    __syncthreads();

    // ---- phase A: y_j = sum_i S[i][j] * x_i, ONE graph-pair per thread ----
    const int j = tid & 63;
    const int p = tid >> 6;              // pair 0..3 -> graphs 2p, 2p+1
    unsigned long long a0=0,a1=0,a2=0,a3=0,a4=0;

    if (j < N_ELEC) {
        const unsigned xb = (unsigned)__cvta_generic_to_shared(&Xp[p * N_ELEC * 6]);
        #pragma unroll 2
        for (int i = 0; i < N_ELEC; i++) {
            float s = Ssh[i * SPITCH + j];             // 32 consecutive, conflict-free
            unsigned long long s2; PACK2(s2, s);
            unsigned long long q0,q1,q2,q3,q4;
            unsigned a = xb + i * 48;                  // broadcast (same addr all lanes)
            asm("ld.shared.v2.u64 {%0,%1}, [%2];"    : "=l"(q0), "=l"(q1) : "r"(a));
            asm("ld.shared.v2.u64 {%0,%1}, [%2+16];" : "=l"(q2), "=l"(q3) : "r"(a));
            asm("ld.shared.u64 %0, [%1+32];"         : "=l"(q4)           : "r"(a));
            FMA2(a0,s2,q0); FMA2(a1,s2,q1); FMA2(a2,s2,q2); FMA2(a3,s2,q3); FMA2(a4,s2,q4);
        }
    }
    __syncthreads();   // reads of Ssh/Xp done; region reused as Ysh

    if (j < N_ELEC) {
        float lo, hi;
        #define YW(acc, c) \
            UNPK2(lo, hi, acc); \
            Ysh[(2*p)   * 320 + (c) * 64 + j] = lo; \
            Ysh[(2*p+1) * 320 + (c) * 64 + j] = hi;
        YW(a0, 0) YW(a1, 1) YW(a2, 2) YW(a3, 3) YW(a4, 4)
        #undef YW
    }
    __syncthreads();

    // ---- phase B: warp per graph, lane = hidden unit o ----
    const int o = tid & 31;
    const int g = tid >> 5;              // 0..7
    const float w0 = Wsh[o][0], w1 = Wsh[o][1], w2 = Wsh[o][2],
                w3 = Wsh[o][3], w4 = Wsh[o][4];
    unsigned long long wd0,wd1,wd2,wd3,wd4,bd;
    PACK2(wd0,w0); PACK2(wd1,w1); PACK2(wd2,w2); PACK2(wd3,w3); PACK2(wd4,w4);
    PACK2(bd, bsh[o]);
    const float f0 = Fsh[0][o], f1 = Fsh[1][o], f2 = Fsh[2][o];

    if (g0 + g < B) {
        const unsigned yb = (unsigned)__cvta_generic_to_shared(&Ysh[g * 320]);
        float ph = 0.f;
        #pragma unroll 2
        for (int j0 = 0; j0 < N_ELEC; j0 += 2) {
            unsigned long long y0,y1,y2,y3,y4;
            unsigned a = yb + j0 * 4;                  // broadcast loads
            asm("ld.shared.u64 %0, [%1];"      : "=l"(y0) : "r"(a));
            asm("ld.shared.u64 %0, [%1+256];"  : "=l"(y1) : "r"(a));
            asm("ld.shared.u64 %0, [%1+512];"  : "=l"(y2) : "r"(a));
            asm("ld.shared.u64 %0, [%1+768];"  : "=l"(y3) : "r"(a));
            asm("ld.shared.u64 %0, [%1+1024];" : "=l"(y4) : "r"(a));
            unsigned long long v = bd;
            FMA2(v, wd0, y0); FMA2(v, wd1, y1); FMA2(v, wd2, y2);
            FMA2(v, wd3, y3); FMA2(v, wd4, y4);
            float lo, hi; UNPK2(lo, hi, v);
            ph += fmaxf(lo, 0.f);
            ph += fmaxf(hi, 0.f);
        }
        float s0 = f0 * ph, s1 = f1 * ph, s2 = f2 * ph;
        #pragma unroll
        for (int off = 16; off > 0; off >>= 1) {
            s0 += __shfl_down_sync(0xffffffffu, s0, off);
            s1 += __shfl_down_sync(0xffffffffu, s1, off);
            s2 += __shfl_down_sync(0xffffffffu, s2, off);
        }
        if (o == 0) {
            float* og = out + (size_t)(g0 + g) * N_CLS;
            og[0] = s0 + fcb[0];
            og[1] = s1 + fcb[1];
            og[2] = s2 + fcb[2];
        }
    }
}

// ---------------------------------------------------------------------------
extern "C" void kernel_launch(void* const* d_in, const int* in_sizes, int n_in,
                              void* d_out, int out_size) {
    const float* x        = (const float*)d_in[0];
    const float* adj_tril = (const float*)d_in[1];
    const float* lin_w    = (const float*)d_in[2];
    const float* lin_b    = (const float*)d_in[3];
    const float* fc_w     = (const float*)d_in[4];
    const float* fc_b     = (const float*)d_in[5];
    // d_in[6] edge_index / d_in[7] batch_idx are structurally redundant.

    const int B = in_sizes[0] / (N_ELEC * IN_CH);

    rgnn_setup_kernel<<<N_ELEC, 128>>>(adj_tril);

    const int grid = (B + GPB - 1) / GPB;
    rgnn_main_kernel<<<grid, NTHR>>>(x, lin_w, lin_b, fc_w, fc_b,
                                     (float*)d_out, B);
}